// round 1
// baseline (speedup 1.0000x reference)
#include <cuda_runtime.h>
#include <cuda_fp16.h>
#include <math.h>

// BG/NBD log-likelihood, N = 8388608 elementwise.
// Strategy:
//   * x in [0,20): all lgamma terms and all 2F1 series coefficients depend only
//     on x -> precompute per-x tables in a tiny setup kernel (fp64 accuracy).
//   * 2F1(r+x, a; a+b+x; z) = sum_k C_k(x) z^k. z <= 0.75 for x>0 rows, so
//     K=48 terms truncates at ~4e-6 relative (tolerance is 1e-3).
//   * Coefficients are in (0,1], all series terms positive -> fp16 storage
//     bounds rel error of F by ~5e-4 -> <=2e-4 on the output ll. Stored as
//     half2 (C_{2j}, C_{2j+1}) for Estrin-by-2: one LDS per 2 terms.
//   * Table layout [pair][x] (x padded to 32): within a warp a fixed-pair load
//     touches <=20 unique 4B words -> conflict-free single-phase LDS.

#define K_TERMS 48
#define NPAIR   (K_TERMS / 2)   // 24 half2 per x-row
#define XROWS   32              // x padded to 32 rows

__device__ __half2 g_coef[NPAIR * XROWS];
__device__ float   g_A[XROWS];
__device__ float   g_sc[4];     // r, alpha, log_alpha, ll0_const

__global__ void setup_kernel(const float* log_r, const float* log_alpha,
                             const float* log_a, const float* log_b)
{
    int x = threadIdx.x;                 // 0..31, one thread per x-row
    double r     = exp((double)log_r[0]);
    double alpha = exp((double)log_alpha[0]);
    double a     = exp((double)log_a[0]);
    double b     = exp((double)log_b[0]);

    double p = r + (double)x;            // 2F1 params for this x
    double q = a;
    double s = a + b + (double)x;

    double C = 1.0;                      // C_0 = 1
    for (int j = 0; j < NPAIR; ++j) {
        int k = 2 * j;
        double c_even = C;
        double c_odd  = c_even * (p + k) * (q + k) / ((s + k) * (k + 1.0));
        g_coef[j * XROWS + x] = __floats2half2_rn((float)c_even, (float)c_odd);
        C = c_odd * (p + k + 1.0) * (q + k + 1.0) / ((s + k + 1.0) * (k + 2.0));
    }

    // term1 + term4 (everything that depends only on x)
    g_A[x] = (float)(lgamma(r + (double)x) - lgamma(r) - lgamma((double)x + 1.0)
                     + log(a) + lgamma(a + b) - lgamma(a)
                     - lgamma(a + b + (double)x) + lgamma(a + (double)x));

    if (x == 0) {
        g_sc[0] = (float)r;
        g_sc[1] = (float)alpha;
        g_sc[2] = log_alpha[0];
        g_sc[3] = (float)(log(b) - log(a + b));   // log b - log(a+b)
    }
}

__global__ void __launch_bounds__(256, 8)
bgnbd_kernel(const int* __restrict__ xs, const float* __restrict__ txs,
             const float* __restrict__ Ts, float* __restrict__ out, int n)
{
    __shared__ __half2 s_coef[NPAIR * XROWS];
    __shared__ float   s_A[XROWS];
    __shared__ float   s_sc[4];

    for (int i = threadIdx.x; i < NPAIR * XROWS; i += blockDim.x)
        s_coef[i] = g_coef[i];
    if (threadIdx.x < XROWS) s_A[threadIdx.x] = g_A[threadIdx.x];
    if (threadIdx.x < 4)     s_sc[threadIdx.x] = g_sc[threadIdx.x];
    __syncthreads();

    const float r = s_sc[0], alpha = s_sc[1], log_alpha = s_sc[2], ll0c = s_sc[3];

    int stride = gridDim.x * blockDim.x;
    for (int i = blockIdx.x * blockDim.x + threadIdx.x; i < n; i += stride) {
        int   xi  = xs[i];
        float Ti  = Ts[i];
        float txi = txs[i];

        float aT     = alpha + Ti;
        float laT    = __logf(aT);
        float common = r * (log_alpha - laT);

        float d  = Ti - txi;                 // > 0 always (t_x < T; t_x=0 if x==0)
        float z  = __fdividef(d, aT);        // <= 0.75 for x>0 rows
        float z2 = z * z;
        int   xc = min(xi, XROWS - 1);

        const __half2* cp = s_coef + xc;

        // Estrin-by-2 Horner over 48 terms:
        // F = sum_j (C_2j + C_{2j+1} z) * (z^2)^j
        float2 ct = __half22float2(cp[(NPAIR - 1) * XROWS]);
        float  F  = fmaf(ct.y, z, ct.x);
        #pragma unroll
        for (int j = NPAIR - 2; j >= 0; --j) {
            float2 c = __half22float2(cp[j * XROWS]);
            F = fmaf(F, z2, fmaf(c.y, z, c.x));
        }

        float ll1 = s_A[xc] + common
                  + (float)xi * (__logf(d) - laT)
                  + __logf(F);

        out[i] = (xi == 0) ? (common + ll0c) : ll1;
    }
}

extern "C" void kernel_launch(void* const* d_in, const int* in_sizes, int n_in,
                              void* d_out, int out_size)
{
    const int*   x         = (const int*)d_in[0];
    const float* t_x       = (const float*)d_in[1];
    const float* T         = (const float*)d_in[2];
    const float* log_r     = (const float*)d_in[3];
    const float* log_alpha = (const float*)d_in[4];
    const float* log_a     = (const float*)d_in[5];
    const float* log_b     = (const float*)d_in[6];
    float*       out       = (float*)d_out;
    int n = in_sizes[0];

    setup_kernel<<<1, XROWS>>>(log_r, log_alpha, log_a, log_b);

    int blocks = 148 * 8;                       // grid-stride, ~8 CTAs/SM
    int maxb   = (n + 255) / 256;
    if (blocks > maxb) blocks = maxb;
    bgnbd_kernel<<<blocks, 256>>>(x, t_x, T, out, n);
}

// round 9
// speedup vs baseline: 1.3274x; 1.3274x over previous
#include <cuda_runtime.h>
#include <math.h>

// BG/NBD log-likelihood, N = 8388608 elementwise, single fused kernel.
//
//   * x in [0,20): all lgamma terms and all 2F1 series coefficients depend
//     only on x -> each BLOCK computes a 32-row fp32 table once (cheap,
//     concurrent across SMs) -- no separate setup kernel (R1's setup kernel
//     cost ~50us serialized on one warp of fp64).
//   * 2F1(r+x, a; a+b+x; z) = sum_k C_k(x) z^k, z <= 0.75 for x>0 rows.
//     K=40 terms -> tail <= 0.75^40/0.25 ~ 4e-5 relative (budget 1e-3).
//   * Coefficients stored as float4 quads (C_4j..C_4j+3): one LDS.128 per
//     4 terms (10 LDS/elem), zero float<->half conversions.
//   * Estrin-by-4: F = sum_j (c0 + c1 z + c2 z^2 + c3 z^3) (z^4)^j.
//   * 4 elements per thread (int4/float4): 4 independent FMA chains hide
//     FFMA latency; vector LDG/STG cut memory-issue 4x.

#define K_TERMS 40
#define NQUAD   (K_TERMS / 4)   // 10 float4 per x-row
#define XROWS   32

__global__ void __launch_bounds__(256, 4)
bgnbd_kernel(const int* __restrict__ xs, const float* __restrict__ txs,
             const float* __restrict__ Ts, float* __restrict__ out, int n,
             const float* __restrict__ p_log_r, const float* __restrict__ p_log_alpha,
             const float* __restrict__ p_log_a, const float* __restrict__ p_log_b)
{
    __shared__ float4 s_coef[NQUAD * XROWS];   // 5120 B
    __shared__ float  s_A[XROWS];
    __shared__ float  s_sc[4];                 // r, log_alpha, ll0_const, alpha

    // ---- per-block table build (threads 0..31), fp32 throughout ----
    if (threadIdx.x < XROWS) {
        int   xv = threadIdx.x;
        float la = p_log_alpha[0];
        float r  = expf(p_log_r[0]);
        float a  = expf(p_log_a[0]);
        float b  = expf(p_log_b[0]);

        float xf = (float)xv;
        float p = r + xf, q = a, s = a + b + xf;

        float C = 1.0f;                        // C_0 = 1
        #pragma unroll 1
        for (int j = 0; j < NQUAD; ++j) {
            float c[4];
            #pragma unroll
            for (int m = 0; m < 4; ++m) {
                float k = (float)(4 * j + m);
                c[m] = C;
                C = C * (p + k) * (q + k) / ((s + k) * (k + 1.0f));
            }
            s_coef[j * XROWS + xv] = make_float4(c[0], c[1], c[2], c[3]);
        }

        s_A[xv] = lgammaf(r + xf) - lgammaf(r) - lgammaf(xf + 1.0f)
                + logf(a) + lgammaf(a + b) - lgammaf(a)
                - lgammaf(a + b + xf) + lgammaf(a + xf);

        if (xv == 0) {
            s_sc[0] = r;
            s_sc[1] = la;
            s_sc[2] = logf(b) - logf(a + b);
            s_sc[3] = expf(la);                // alpha
        }
    }
    __syncthreads();

    const float r         = s_sc[0];
    const float log_alpha = s_sc[1];
    const float ll0c      = s_sc[2];
    const float alpha     = s_sc[3];
    const float rla       = r * log_alpha;

    const int4*   xs4 = (const int4*)xs;
    const float4* tx4 = (const float4*)txs;
    const float4* T4  = (const float4*)Ts;
    float4*       o4  = (float4*)out;

    int n4     = n >> 2;
    int stride = gridDim.x * blockDim.x;

    for (int i = blockIdx.x * blockDim.x + threadIdx.x; i < n4; i += stride) {
        int4   xv = xs4[i];
        float4 tv = tx4[i];
        float4 Tv = T4[i];

        int   xl[4] = {xv.x, xv.y, xv.z, xv.w};
        float Tl[4] = {Tv.x, Tv.y, Tv.z, Tv.w};
        float tl[4] = {tv.x, tv.y, tv.z, tv.w};

        int   xc[4];
        float aT[4], z[4], z2[4], z4[4], F[4];

        #pragma unroll
        for (int l = 0; l < 4; ++l) {
            xc[l] = min(xl[l], XROWS - 1);
            aT[l] = alpha + Tl[l];
            z[l]  = __fdividef(Tl[l] - tl[l], aT[l]);   // t_x < T always
            z2[l] = z[l] * z[l];
            z4[l] = z2[l] * z2[l];
            float4 c = s_coef[(NQUAD - 1) * XROWS + xc[l]];
            // top group: c0 + c1 z + c2 z^2 + c3 z^3
            F[l] = fmaf(z2[l], fmaf(c.w, z[l], c.z), fmaf(c.y, z[l], c.x));
        }

        #pragma unroll
        for (int j = NQUAD - 2; j >= 0; --j) {
            #pragma unroll
            for (int l = 0; l < 4; ++l) {
                float4 c = s_coef[j * XROWS + xc[l]];
                float g  = fmaf(z2[l], fmaf(c.w, z[l], c.z), fmaf(c.y, z[l], c.x));
                F[l] = fmaf(F[l], z4[l], g);
            }
        }

        float res[4];
        #pragma unroll
        for (int l = 0; l < 4; ++l) {
            float laT    = __logf(aT[l]);
            float common = rla - r * laT;
            // x*(log d - log aT) == x * log z
            float ll1 = s_A[xc[l]] + common
                      + (float)xl[l] * __logf(z[l])
                      + __logf(F[l]);
            res[l] = (xl[l] == 0) ? (common + ll0c) : ll1;
        }

        o4[i] = make_float4(res[0], res[1], res[2], res[3]);
    }

    // scalar tail (n not divisible by 4)
    int rem_base = n4 << 2;
    if (blockIdx.x == 0) {
        for (int i = rem_base + threadIdx.x; i < n; i += blockDim.x) {
            int   xi = xs[i];
            float Ti = Ts[i];
            float aT = alpha + Ti;
            float zz = __fdividef(Ti - txs[i], aT);
            float zz2 = zz * zz;
            float zz4 = zz2 * zz2;
            int   xcs = min(xi, XROWS - 1);
            float4 ct = s_coef[(NQUAD - 1) * XROWS + xcs];
            float Fs = fmaf(zz2, fmaf(ct.w, zz, ct.z), fmaf(ct.y, zz, ct.x));
            #pragma unroll
            for (int j = NQUAD - 2; j >= 0; --j) {
                float4 c = s_coef[j * XROWS + xcs];
                float g = fmaf(zz2, fmaf(c.w, zz, c.z), fmaf(c.y, zz, c.x));
                Fs = fmaf(Fs, zz4, g);
            }
            float laT    = __logf(aT);
            float common = rla - r * laT;
            float ll1 = s_A[xcs] + common + (float)xi * __logf(zz) + __logf(Fs);
            out[i] = (xi == 0) ? (common + ll0c) : ll1;
        }
    }
}

extern "C" void kernel_launch(void* const* d_in, const int* in_sizes, int n_in,
                              void* d_out, int out_size)
{
    const int*   x         = (const int*)d_in[0];
    const float* t_x       = (const float*)d_in[1];
    const float* T         = (const float*)d_in[2];
    const float* log_r     = (const float*)d_in[3];
    const float* log_alpha = (const float*)d_in[4];
    const float* log_a     = (const float*)d_in[5];
    const float* log_b     = (const float*)d_in[6];
    float*       out       = (float*)d_out;
    int n = in_sizes[0];

    int blocks = 148 * 8;                       // grid-stride over n/4 vectors
    int maxb   = (n / 4 + 255) / 256;
    if (maxb < 1) maxb = 1;
    if (blocks > maxb) blocks = maxb;
    bgnbd_kernel<<<blocks, 256>>>(x, t_x, T, out, n,
                                  log_r, log_alpha, log_a, log_b);
}